// round 9
// baseline (speedup 1.0000x reference)
#include <cuda_runtime.h>
#include <cuda_bf16.h>

// out[k][d] = mult_k * sum_i W_k[eb_input[i]][d]   (offsets mathematically dead:
// every index position lands in some bag and all bags are summed).
//
// hist : 1 u32 global RED per index, 1x int4 per thread (measured 19.6us, ~floor).
// sweep: 8 rows/thread (2x uint4 counts, 6x float4 per table) -> 2x MLP vs R1.
// final: separate 1-block kernel (fusion measured slower twice -> keep 3 launches).

#define MAX_EMB 2000000

// 8MB u32 counts. Zeroed at load; sweep re-zeroes after reading -> clean state
// for every graph replay.
__device__ unsigned int g_count[MAX_EMB];
// 9 double accumulators padded to 512B stride (distinct L2 slices).
__device__ double g_acc[9 * 64];

// ---------------------------------------------------------------------------
// Kernel 1: histogram. One int4 (4 indices) per thread, 4 REDs.
// ---------------------------------------------------------------------------
__global__ void k_hist(const int* __restrict__ idx, int n_idx) {
    int t = blockIdx.x * blockDim.x + threadIdx.x;
    int n4 = n_idx >> 2;
    if (t < n4) {
        int4 a = __ldcs((const int4*)idx + t);   // index stream: evict-first
        atomicAdd(&g_count[a.x], 1u);
        atomicAdd(&g_count[a.y], 1u);
        atomicAdd(&g_count[a.z], 1u);
        atomicAdd(&g_count[a.w], 1u);
    }
    if (blockIdx.x == 0) {                       // scalar tail
        int rem = n_idx & 3;
        if ((int)threadIdx.x < rem)
            atomicAdd(&g_count[idx[(n4 << 2) + threadIdx.x]], 1u);
    }
}

// ---------------------------------------------------------------------------
// Kernel 2: weighted sweep, 8 rows per thread.
// ---------------------------------------------------------------------------
__global__ void k_sweep(const float* __restrict__ W0,
                        const float* __restrict__ W1,
                        const float* __restrict__ W2,
                        int num_emb) {
    int t = blockIdx.x * blockDim.x + threadIdx.x;
    int r0 = t * 8;

    float acc[9];
#pragma unroll
    for (int k = 0; k < 9; k++) acc[k] = 0.0f;

    if (r0 + 8 <= num_emb) {
        // counts: 8 rows = 2x uint4 read + zero
        uint4 ca = *(const uint4*)&g_count[r0];
        uint4 cb = *(const uint4*)&g_count[r0 + 4];
        *(uint4*)&g_count[r0]     = make_uint4(0u, 0u, 0u, 0u);
        *(uint4*)&g_count[r0 + 4] = make_uint4(0u, 0u, 0u, 0u);
        float c[8];
        c[0] = (float)ca.x; c[1] = (float)ca.y; c[2] = (float)ca.z; c[3] = (float)ca.w;
        c[4] = (float)cb.x; c[5] = (float)cb.y; c[6] = (float)cb.z; c[7] = (float)cb.w;

        const float* Ws[3] = {W0, W1, W2};
#pragma unroll
        for (int k = 0; k < 3; k++) {
            const float4* Wv = (const float4*)Ws[k] + 6 * t;   // 24 floats = 8 rows
            float w[24];
#pragma unroll
            for (int q = 0; q < 6; q++) {
                float4 v = __ldg(Wv + q);
                w[4 * q + 0] = v.x; w[4 * q + 1] = v.y;
                w[4 * q + 2] = v.z; w[4 * q + 3] = v.w;
            }
#pragma unroll
            for (int j = 0; j < 8; j++) {
                acc[3 * k + 0] += c[j] * w[3 * j + 0];
                acc[3 * k + 1] += c[j] * w[3 * j + 1];
                acc[3 * k + 2] += c[j] * w[3 * j + 2];
            }
        }
    } else if (r0 < num_emb) {
        for (int r = r0; r < num_emb; r++) {
            float cc = (float)g_count[r];
            g_count[r] = 0u;
            const float* Ws[3] = {W0, W1, W2};
#pragma unroll
            for (int k = 0; k < 3; k++) {
                acc[3 * k + 0] += cc * Ws[k][3 * r + 0];
                acc[3 * k + 1] += cc * Ws[k][3 * r + 1];
                acc[3 * k + 2] += cc * Ws[k][3 * r + 2];
            }
        }
    }

    // warp reduction
    unsigned lane = threadIdx.x & 31u;
    unsigned warp = threadIdx.x >> 5;
#pragma unroll
    for (int k = 0; k < 9; k++) {
#pragma unroll
        for (int o = 16; o > 0; o >>= 1)
            acc[k] += __shfl_down_sync(0xffffffffu, acc[k], o);
    }

    __shared__ float s_red[8][9];
    if (lane == 0) {
#pragma unroll
        for (int k = 0; k < 9; k++) s_red[warp][k] = acc[k];
    }
    __syncthreads();

    if (threadIdx.x < 9) {
        double s = 0.0;
        int nw = (blockDim.x + 31) >> 5;
        for (int w = 0; w < nw; w++) s += (double)s_red[w][threadIdx.x];
        atomicAdd(&g_acc[threadIdx.x * 64], s);
    }
}

// ---------------------------------------------------------------------------
// Kernel 3: scale, write output, re-zero accumulators for next replay.
// ---------------------------------------------------------------------------
__global__ void k_final(float* __restrict__ out) {
    int i = threadIdx.x;
    if (i < 9) {
        const float mult[3] = {5.0f, 10.0f, 6.0f};
        double v = g_acc[i * 64];
        g_acc[i * 64] = 0.0;
        out[i] = (float)((double)mult[i / 3] * v);
    }
}

// ---------------------------------------------------------------------------
extern "C" void kernel_launch(void* const* d_in, const int* in_sizes, int n_in,
                              void* d_out, int out_size) {
    const int*   idx = (const int*)d_in[0];
    // d_in[1] = eb_offset : mathematically unused
    const float* W0  = (const float*)d_in[2];
    const float* W1  = (const float*)d_in[3];
    const float* W2  = (const float*)d_in[4];
    int n_idx   = in_sizes[0];
    int num_emb = in_sizes[2] / 3;

    int n4 = n_idx >> 2;
    int hist_blocks = (n4 + 255) / 256;
    if (hist_blocks < 1) hist_blocks = 1;
    k_hist<<<hist_blocks, 256>>>(idx, n_idx);

    int sweep_threads = (num_emb + 7) / 8;
    int sweep_blocks = (sweep_threads + 255) / 256;
    if (sweep_blocks < 1) sweep_blocks = 1;
    k_sweep<<<sweep_blocks, 256>>>(W0, W1, W2, num_emb);

    k_final<<<1, 32>>>((float*)d_out);
}